// round 1
// baseline (speedup 1.0000x reference)
#include <cuda_runtime.h>
#include <cstdint>
#include <cstddef>

// Problem constants
#define B_SZ   16384
#define N_N    5
#define D_D    128
#define F_F    4
#define TD_D   384
#define HID_C  150
#define R_R    (B_SZ * N_N)        // 81920 rows for the MLP

// ---------------------------------------------------------------------------
// Device scratch (static allocation is allowed; cudaMalloc is not)
// ---------------------------------------------------------------------------
__device__ float g_te[(size_t)R_R * D_D];      // 81920 x 128 text embeddings
__device__ float g_P[(size_t)R_R * 8];         // per (b,n,f,o): exp(logit)*softplus(dot)
__device__ float g_partial[5 * 8 * 2048];      // block partials of exp-sums
__device__ float g_invS[40];                   // 1 / softmax denominators per (n,f,o)

__device__ __forceinline__ float leaky(float x) { return x > 0.f ? x : 0.01f * x; }
__device__ __forceinline__ float softplusf(float x) {
    return fmaxf(x, 0.f) + log1pf(expf(-fabsf(x)));
}

// packed fp32x2 FMA: acc = a*b + acc (two independent fp32 lanes)
#define FMA2(acc, a, b) \
    asm("fma.rn.f32x2 %0, %1, %2, %0;" : "+l"(acc) : "l"(a), "l"(b))

// ---------------------------------------------------------------------------
// Kernel 1: fused text MLP
//   te = leaky( leaky(text @ W1^T + b1) @ W2^T + b2 )
// Block: 256 threads, 64 rows per block.
// Phase A: GEMM1 (K=384 -> 150 hidden, padded to 160 cols), reg tile 8x5 (f32x2 over rows)
// Phase B: GEMM2 (150 -> 128), reg tile 8x4
// ---------------------------------------------------------------------------
__global__ __launch_bounds__(256) void mlp_kernel(
    const float* __restrict__ text,
    const float* __restrict__ w1, const float* __restrict__ b1,
    const float* __restrict__ w2, const float* __restrict__ b2)
{
    // Shared memory (47280 B total, regions overlap in time):
    //   Hs  : [150][66]  at offset 0          (phase A epilogue -> phase B input)
    //   W2s : [15][128]  at offset 9900 f     (phase B weight panel)
    //   Xs  : [16][64]   at offset 0          (phase A, dead before Hs written)
    //   W1s : [16][160]  at offset 1024 f     (phase A)
    __shared__ __align__(16) float sm[11820];
    float* Hs  = sm;            // 9900 floats
    float* W2s = sm + 9900;     // 1920 floats
    float* Xs  = sm;            // 1024 floats
    float* W1s = sm + 1024;     // 2560 floats

    const int tid = threadIdx.x;
    const int tx = tid & 31;        // 0..31 (column group)
    const int ty = tid >> 5;        // 0..7  (row group: rows ty*8 .. ty*8+7)
    const int row0 = blockIdx.x * 64;

    // ---- Phase A: GEMM1 ----
    unsigned long long acc[4][5];
    #pragma unroll
    for (int i = 0; i < 4; i++)
        #pragma unroll
        for (int j = 0; j < 5; j++) acc[i][j] = 0ull;

    for (int kp = 0; kp < TD_D; kp += 16) {
        // load X tile (16 k x 64 rows), transposed into Xs[k][r]
        {
            int r = tid >> 2, kq = tid & 3;
            float4 v = *(const float4*)(text + (size_t)(row0 + r) * TD_D + kp + kq * 4);
            Xs[(kq * 4 + 0) * 64 + r] = v.x;
            Xs[(kq * 4 + 1) * 64 + r] = v.y;
            Xs[(kq * 4 + 2) * 64 + r] = v.z;
            Xs[(kq * 4 + 3) * 64 + r] = v.w;
        }
        // load W1 panel (16 k x 160 cols, zero-padded beyond 150)
        #pragma unroll
        for (int i = 0; i < 10; i++) {
            int e = tid + i * 256;
            int k = e & 15, h = e >> 4;
            W1s[k * 160 + h] = (h < HID_C) ? w1[h * TD_D + kp + k] : 0.f;
        }
        __syncthreads();
        #pragma unroll
        for (int k = 0; k < 16; k++) {
            const unsigned long long* xr = (const unsigned long long*)(Xs + k * 64);
            unsigned long long x0 = xr[ty * 4 + 0];
            unsigned long long x1 = xr[ty * 4 + 1];
            unsigned long long x2 = xr[ty * 4 + 2];
            unsigned long long x3 = xr[ty * 4 + 3];
            #pragma unroll
            for (int j = 0; j < 5; j++) {
                float w = W1s[k * 160 + tx + 32 * j];
                unsigned long long wp;
                asm("mov.b64 %0, {%1, %1};" : "=l"(wp) : "f"(w));
                FMA2(acc[0][j], x0, wp);
                FMA2(acc[1][j], x1, wp);
                FMA2(acc[2][j], x2, wp);
                FMA2(acc[3][j], x3, wp);
            }
        }
        __syncthreads();
    }

    // epilogue A: bias + leaky -> Hs[col][row] (stride 66, only cols < 150)
    #pragma unroll
    for (int j = 0; j < 5; j++) {
        int col = tx + 32 * j;
        if (col < HID_C) {
            float bias = __ldg(b1 + col);
            #pragma unroll
            for (int i = 0; i < 4; i++) {
                float lo, hi;
                asm("mov.b64 {%0, %1}, %2;" : "=f"(lo), "=f"(hi) : "l"(acc[i][j]));
                int r = ty * 8 + 2 * i;
                Hs[col * 66 + r]     = leaky(lo + bias);
                Hs[col * 66 + r + 1] = leaky(hi + bias);
            }
        }
    }

    // ---- Phase B: GEMM2 (150 -> 128) ----
    unsigned long long acc2[4][4];
    #pragma unroll
    for (int i = 0; i < 4; i++)
        #pragma unroll
        for (int j = 0; j < 4; j++) acc2[i][j] = 0ull;

    for (int hp = 0; hp < HID_C; hp += 15) {
        __syncthreads();  // Hs visible on first iter; W2s safe to overwrite on later iters
        for (int e = tid; e < 15 * 128; e += 256) {
            int k = e % 15, o = e / 15;
            W2s[k * 128 + o] = w2[o * HID_C + hp + k];
        }
        __syncthreads();
        #pragma unroll
        for (int k = 0; k < 15; k++) {
            const unsigned long long* xr = (const unsigned long long*)(Hs + (hp + k) * 66);
            unsigned long long x0 = xr[ty * 4 + 0];
            unsigned long long x1 = xr[ty * 4 + 1];
            unsigned long long x2 = xr[ty * 4 + 2];
            unsigned long long x3 = xr[ty * 4 + 3];
            #pragma unroll
            for (int j = 0; j < 4; j++) {
                float w = W2s[k * 128 + tx + 32 * j];
                unsigned long long wp;
                asm("mov.b64 %0, {%1, %1};" : "=l"(wp) : "f"(w));
                FMA2(acc2[0][j], x0, wp);
                FMA2(acc2[1][j], x1, wp);
                FMA2(acc2[2][j], x2, wp);
                FMA2(acc2[3][j], x3, wp);
            }
        }
    }

    // epilogue B: bias + leaky -> g_te
    #pragma unroll
    for (int j = 0; j < 4; j++) {
        int col = tx + 32 * j;
        float bias = __ldg(b2 + col);
        #pragma unroll
        for (int i = 0; i < 4; i++) {
            float lo, hi;
            asm("mov.b64 {%0, %1}, %2;" : "=f"(lo), "=f"(hi) : "l"(acc2[i][j]));
            int r = ty * 8 + 2 * i;
            g_te[(size_t)(row0 + r) * D_D + col]       = leaky(lo + bias);
            g_te[(size_t)(row0 + r + 1) * D_D + col]   = leaky(hi + bias);
        }
    }
}

// ---------------------------------------------------------------------------
// Kernel 2: attention stage. One warp per (b, n). grid = (2048, 5), block 256.
// lane covers dims [lane*4, lane*4+4); f = lane>>3; 8 lanes per factor group.
// Computes exp(logits) and softplus-weighted payloads; emits deterministic
// block partials of the batch-axis softmax denominators.
// ---------------------------------------------------------------------------
__global__ __launch_bounds__(256) void attn_kernel(
    const int* __restrict__ batch,
    const float* __restrict__ user_table,
    const float* __restrict__ item_table,
    const float* __restrict__ aw1,
    const float* __restrict__ ab1,
    const float* __restrict__ aw2)
{
    __shared__ float sm_e[8][8];
    const int tid = threadIdx.x;
    const int w = tid >> 5, lane = tid & 31;
    const int b = blockIdx.x * 8 + w;
    const int n = blockIdx.y;
    const int bn = b * N_N + n;
    const int f = lane >> 3;
    const int s = lane & 7;

    const int user = batch[b * 6];
    const int item = batch[b * 6 + 1 + n];
    float4 u  = *(const float4*)(user_table + (size_t)user * D_D + lane * 4);
    float4 it = *(const float4*)(item_table + (size_t)item * D_D + lane * 4);
    float4 t  = *(const float4*)(g_te + (size_t)bn * D_D + lane * 4);

    float ss = u.x*u.x + u.y*u.y + u.z*u.z + u.w*u.w
             + it.x*it.x + it.y*it.y + it.z*it.z + it.w*it.w
             + t.x*t.x + t.y*t.y + t.z*t.z + t.w*t.w;
    float dui = u.x*it.x + u.y*it.y + u.z*it.z + u.w*it.w;
    float dut = u.x*t.x  + u.y*t.y  + u.z*t.z  + u.w*t.w;

    const float* A0 = aw1 + (f * 2 + 0) * 96;
    const float* A1 = aw1 + (f * 2 + 1) * 96;
    const int k0 = s * 4;
    float p0 = u.x*A0[k0] + u.y*A0[k0+1] + u.z*A0[k0+2] + u.w*A0[k0+3]
             + it.x*A0[32+k0] + it.y*A0[33+k0] + it.z*A0[34+k0] + it.w*A0[35+k0]
             + t.x*A0[64+k0]  + t.y*A0[65+k0]  + t.z*A0[66+k0]  + t.w*A0[67+k0];
    float p1 = u.x*A1[k0] + u.y*A1[k0+1] + u.z*A1[k0+2] + u.w*A1[k0+3]
             + it.x*A1[32+k0] + it.y*A1[33+k0] + it.z*A1[34+k0] + it.w*A1[35+k0]
             + t.x*A1[64+k0]  + t.y*A1[65+k0]  + t.z*A1[66+k0]  + t.w*A1[67+k0];

    #pragma unroll
    for (int m = 1; m < 8; m <<= 1) {
        ss  += __shfl_xor_sync(0xffffffffu, ss,  m);
        dui += __shfl_xor_sync(0xffffffffu, dui, m);
        dut += __shfl_xor_sync(0xffffffffu, dut, m);
        p0  += __shfl_xor_sync(0xffffffffu, p0,  m);
        p1  += __shfl_xor_sync(0xffffffffu, p1,  m);
    }

    float inv = 1.0f / fmaxf(sqrtf(ss), 1e-12f);
    float h0 = tanhf(p0 * inv + __ldg(ab1 + f * 2 + 0));
    float h1 = tanhf(p1 * inv + __ldg(ab1 + f * 2 + 1));
    float l0 = h0 * __ldg(aw2 + f * 4 + 0) + h1 * __ldg(aw2 + f * 4 + 1);
    float l1 = h0 * __ldg(aw2 + f * 4 + 2) + h1 * __ldg(aw2 + f * 4 + 3);
    // |logits| <= ~1.5, so un-shifted exp is safe (identical to softmax w/ max-shift)
    float e0 = expf(l0), e1 = expf(l1);

    if (s == 0) {
        g_P[(size_t)bn * 8 + f * 2 + 0] = e0 * softplusf(dui);
        g_P[(size_t)bn * 8 + f * 2 + 1] = e1 * softplusf(dut);
        sm_e[w][f * 2 + 0] = e0;
        sm_e[w][f * 2 + 1] = e1;
    }
    __syncthreads();
    if (tid < 8) {
        float sum = 0.f;
        #pragma unroll
        for (int q = 0; q < 8; q++) sum += sm_e[q][tid];
        g_partial[(n * 8 + tid) * 2048 + blockIdx.x] = sum;
    }
}

// ---------------------------------------------------------------------------
// Kernel 2.5: deterministic tree reduction of the 40 softmax denominators
// ---------------------------------------------------------------------------
__global__ __launch_bounds__(256) void reduce_kernel()
{
    __shared__ float sm[256];
    const int q = blockIdx.x;          // 0..39
    float s = 0.f;
    for (int i = threadIdx.x; i < 2048; i += 256)
        s += g_partial[q * 2048 + i];
    sm[threadIdx.x] = s;
    __syncthreads();
    for (int st = 128; st > 0; st >>= 1) {
        if (threadIdx.x < st) sm[threadIdx.x] += sm[threadIdx.x + st];
        __syncthreads();
    }
    if (threadIdx.x == 0) g_invS[q] = 1.0f / sm[0];
}

// ---------------------------------------------------------------------------
// Kernel 3: combine -> ratings (B, N)
// ---------------------------------------------------------------------------
__global__ __launch_bounds__(256) void final_kernel(float* __restrict__ out)
{
    const int idx = blockIdx.x * 256 + threadIdx.x;
    if (idx >= R_R) return;
    const int n = idx % N_N;
    float r = 0.f;
    #pragma unroll
    for (int f = 0; f < 4; f++) {
        r += g_P[(size_t)idx * 8 + f * 2 + 0] * g_invS[n * 8 + f * 2 + 0];
        r += g_P[(size_t)idx * 8 + f * 2 + 1] * g_invS[n * 8 + f * 2 + 1];
    }
    out[idx] = r;
}

// ---------------------------------------------------------------------------
extern "C" void kernel_launch(void* const* d_in, const int* in_sizes, int n_in,
                              void* d_out, int out_size)
{
    const int*   batch = (const int*)d_in[0];
    const float* text  = (const float*)d_in[1];
    const float* ut    = (const float*)d_in[2];
    const float* itt   = (const float*)d_in[3];
    const float* w1    = (const float*)d_in[4];
    const float* b1    = (const float*)d_in[5];
    const float* w2    = (const float*)d_in[6];
    const float* b2    = (const float*)d_in[7];
    const float* aw1   = (const float*)d_in[8];
    const float* ab1   = (const float*)d_in[9];
    const float* aw2   = (const float*)d_in[10];
    float* out = (float*)d_out;

    mlp_kernel<<<R_R / 64, 256>>>(text, w1, b1, w2, b2);
    attn_kernel<<<dim3(B_SZ / 8, N_N), 256>>>(batch, ut, itt, aw1, ab1, aw2);
    reduce_kernel<<<40, 256>>>();
    final_kernel<<<(R_R + 255) / 256, 256>>>(out);
}

// round 3
// speedup vs baseline: 2.2989x; 2.2989x over previous
#include <cuda_runtime.h>
#include <cuda_bf16.h>
#include <cstdint>
#include <cstddef>

// ---------------------------------------------------------------------------
// Problem constants
// ---------------------------------------------------------------------------
#define B_SZ   16384
#define N_N    5
#define D_D    128
#define TD_D   384
#define HID_C  150
#define R_R    (B_SZ * N_N)     // 81920 MLP rows
#define MROWS  128              // rows per CTA

// ---------------------------------------------------------------------------
// Device scratch
// ---------------------------------------------------------------------------
__device__ float g_te[(size_t)R_R * D_D];
__device__ float g_P[(size_t)R_R * 8];
__device__ float g_partial[5 * 8 * 2048];
__device__ float g_invS[40];
__device__ __align__(16) __nv_bfloat16 g_w1h[160 * 384];  // W1 hi, rows 150..159 zero
__device__ __align__(16) __nv_bfloat16 g_w1l[160 * 384];  // W1 lo
__device__ __align__(16) __nv_bfloat16 g_w2h[128 * 192];  // W2 hi, cols 150..191 zero
__device__ __align__(16) __nv_bfloat16 g_w2l[128 * 192];  // W2 lo

__device__ __forceinline__ float leaky(float x) { return x > 0.f ? x : 0.01f * x; }
__device__ __forceinline__ float softplusf(float x) {
    return fmaxf(x, 0.f) + log1pf(expf(-fabsf(x)));
}

// ---------------------------------------------------------------------------
// MMA helpers (portable PTX: valid on plain sm_103 target)
// ---------------------------------------------------------------------------
#define LDSM4(r, a)                                                            \
    asm volatile("ldmatrix.sync.aligned.m8n8.x4.shared.b16 {%0,%1,%2,%3}, [%4];" \
        : "=r"((r)[0]), "=r"((r)[1]), "=r"((r)[2]), "=r"((r)[3]) : "r"(a))

#define MMA(d, a, b0_, b1_)                                                    \
    asm volatile("mma.sync.aligned.m16n8k16.row.col.f32.bf16.bf16.f32 "        \
        "{%0,%1,%2,%3}, {%4,%5,%6,%7}, {%8,%9}, {%0,%1,%2,%3};"                \
        : "+f"((d)[0]), "+f"((d)[1]), "+f"((d)[2]), "+f"((d)[3])               \
        : "r"((a)[0]), "r"((a)[1]), "r"((a)[2]), "r"((a)[3]), "r"(b0_), "r"(b1_))

__device__ __forceinline__ uint32_t smem_u32(const void* p) {
    uint32_t a;
    asm("{ .reg .u64 t; cvta.to.shared.u64 t, %1; cvt.u32.u64 %0, t; }" : "=r"(a) : "l"(p));
    return a;
}

// Split two fp32 into packed bf16x2 (hi part) + packed bf16x2 (residual part).
// Low 16 bits hold element v0 (memory order).
__device__ __forceinline__ void split2(float v0, float v1, uint32_t& ph, uint32_t& pl) {
    asm("cvt.rn.bf16x2.f32 %0, %1, %2;" : "=r"(ph) : "f"(v1), "f"(v0));
    float h0 = __uint_as_float(ph << 16);
    float h1 = __uint_as_float(ph & 0xffff0000u);
    float r0 = v0 - h0, r1 = v1 - h1;
    asm("cvt.rn.bf16x2.f32 %0, %1, %2;" : "=r"(pl) : "f"(r1), "f"(r0));
}

__device__ __forceinline__ void split_bf16s(float x, unsigned short& h, unsigned short& l) {
    __nv_bfloat16 bh = __float2bfloat16(x);
    float r = x - __bfloat162float(bh);
    h = __bfloat16_as_ushort(bh);
    l = __bfloat16_as_ushort(__float2bfloat16(r));
}

// ---------------------------------------------------------------------------
// Shared memory byte offsets (strides chosen conflict-free for ldmatrix:
//   144 % 128 = 16, 336 % 128 = 80 -> 8 successive rows hit distinct 16B segs)
//   XH/XL:  X K-chunk [128 rows][64 k], stride 144B       (GEMM1)
//   W1H/L:  W1 K-chunk [160 n][64 k], stride 144B         (GEMM1)
//   HH/HL:  H [128 rows][160 k], stride 336B  (overlays X/W1 after GEMM1)
//   W2H/L:  W2 [128 n][160 k], stride 336B
// ---------------------------------------------------------------------------
#define XH_O   0u
#define XL_O   18432u
#define W1H_O  36864u
#define W1L_O  59904u
#define HH_O   0u
#define HL_O   43008u
#define W2H_O  86016u
#define W2L_O  129024u
#define SMEM_BYTES 172032

// ---------------------------------------------------------------------------
// Kernel 0: split W1/W2 into bf16 hi/lo with zero padding
// ---------------------------------------------------------------------------
__global__ __launch_bounds__(256) void setup_kernel(
    const float* __restrict__ w1, const float* __restrict__ w2)
{
    int i = blockIdx.x * 256 + threadIdx.x;
    if (i < 160 * 384) {
        int r = i / 384, c = i % 384;
        float v = (r < HID_C) ? w1[r * TD_D + c] : 0.f;
        unsigned short h, l;
        split_bf16s(v, h, l);
        g_w1h[i] = __ushort_as_bfloat16(h);
        g_w1l[i] = __ushort_as_bfloat16(l);
    } else {
        int j = i - 160 * 384;
        if (j < 128 * 192) {
            int r = j / 192, c = j % 192;
            float v = (c < HID_C) ? w2[r * HID_C + c] : 0.f;
            unsigned short h, l;
            split_bf16s(v, h, l);
            g_w2h[j] = __ushort_as_bfloat16(h);
            g_w2l[j] = __ushort_as_bfloat16(l);
        }
    }
}

// ---------------------------------------------------------------------------
// Kernel 1: fused text MLP on tensor cores via mma.sync (bf16 3-term split)
//   GEMM1: H[128,160] = X[128,384] @ W1pad^T ; leaky+bias -> smem bf16 hi/lo
//   GEMM2: te[128,128] = H[128,160] @ W2pad^T ; leaky+bias -> gmem
// 256 threads = 8 warps; warp w owns rows [w*16, w*16+16).
// ---------------------------------------------------------------------------
__global__ __launch_bounds__(256, 1)
void mlp_mma_kernel(const float* __restrict__ text,
                    const float* __restrict__ b1,
                    const float* __restrict__ b2)
{
    extern __shared__ __align__(16) char smp[];
    const uint32_t s0 = smem_u32(smp);

    const int tid = threadIdx.x;
    const int wid = tid >> 5, lane = tid & 31;
    const int row0 = blockIdx.x * MROWS;
    const int m0 = wid * 16;

    // ldmatrix per-lane address components
    const uint32_t a_row  = (lane & 7) + ((lane >> 3) & 1) * 8;
    const uint32_t a_col8 = (uint32_t)(lane >> 4) * 8;
    const uint32_t b_row  = (lane & 7) + (lane >> 4) * 8;
    const uint32_t b_col8 = (uint32_t)((lane >> 3) & 1) * 8;

    const uint32_t xh_a  = s0 + XH_O  + (m0 + a_row) * 144 + a_col8 * 2;
    const uint32_t xl_a  = s0 + XL_O  + (m0 + a_row) * 144 + a_col8 * 2;
    const uint32_t w1h_b = s0 + W1H_O + b_row * 144 + b_col8 * 2;
    const uint32_t w1l_b = s0 + W1L_O + b_row * 144 + b_col8 * 2;
    const uint32_t hh_a  = s0 + HH_O  + (m0 + a_row) * 336 + a_col8 * 2;
    const uint32_t hl_a  = s0 + HL_O  + (m0 + a_row) * 336 + a_col8 * 2;
    const uint32_t w2h_b = s0 + W2H_O + b_row * 336 + b_col8 * 2;
    const uint32_t w2l_b = s0 + W2L_O + b_row * 336 + b_col8 * 2;

    // ---- preload W2 into smem (hi/lo), k = 0..159, stride 336B ----
    #pragma unroll
    for (int j = 0; j < 10; j++) {
        int idx = tid + j * 256;               // < 2560
        int r = idx / 20, seg = idx % 20;
        *(uint4*)(smp + W2H_O + r * 336 + seg * 16) =
            *(const uint4*)(g_w2h + r * 192 + seg * 8);
        *(uint4*)(smp + W2L_O + r * 336 + seg * 16) =
            *(const uint4*)(g_w2l + r * 192 + seg * 8);
    }

    // ---- GEMM1: 6 K-chunks of 64 ----
    float acc[20][4];
    #pragma unroll
    for (int t = 0; t < 20; t++)
        #pragma unroll
        for (int r = 0; r < 4; r++) acc[t][r] = 0.f;

    const int xr = tid >> 1;                   // row this thread converts
    const int xh = (tid & 1) * 32;             // 32-col half

    for (int kc = 0; kc < 6; kc++) {
        __syncthreads();   // previous chunk's ldmatrix reads complete
        // X chunk: fp32 -> bf16 hi/lo
        {
            const float* src = text + (size_t)(row0 + xr) * TD_D + kc * 64 + xh;
            char* dh = smp + XH_O + xr * 144 + xh * 2;
            char* dl = smp + XL_O + xr * 144 + xh * 2;
            #pragma unroll
            for (int i = 0; i < 8; i++) {
                float4 v = *(const float4*)(src + i * 4);
                uint32_t pha, pla, phb, plb;
                split2(v.x, v.y, pha, pla);
                split2(v.z, v.w, phb, plb);
                *(uint2*)(dh + i * 8) = make_uint2(pha, phb);
                *(uint2*)(dl + i * 8) = make_uint2(pla, plb);
            }
        }
        // W1 chunk copy (pre-split bf16)
        #pragma unroll
        for (int j = 0; j < 5; j++) {
            int idx = tid + j * 256;           // < 1280
            int r = idx >> 3, seg = idx & 7;
            *(uint4*)(smp + W1H_O + r * 144 + seg * 16) =
                *(const uint4*)(g_w1h + r * 384 + kc * 64 + seg * 8);
            *(uint4*)(smp + W1L_O + r * 144 + seg * 16) =
                *(const uint4*)(g_w1l + r * 384 + kc * 64 + seg * 8);
        }
        __syncthreads();

        #pragma unroll
        for (int ks = 0; ks < 4; ks++) {
            const uint32_t off = ks * 32;
            uint32_t ah[4], al[4];
            LDSM4(ah, xh_a + off);
            LDSM4(al, xl_a + off);
            #pragma unroll
            for (int np = 0; np < 10; np += 2) {
                uint32_t bh0[4], bl0[4], bh1[4], bl1[4];
                LDSM4(bh0, w1h_b + np * 2304 + off);
                LDSM4(bl0, w1l_b + np * 2304 + off);
                LDSM4(bh1, w1h_b + (np + 1) * 2304 + off);
                LDSM4(bl1, w1l_b + (np + 1) * 2304 + off);
                float* d0 = acc[np * 2 + 0];
                float* d1 = acc[np * 2 + 1];
                float* d2 = acc[np * 2 + 2];
                float* d3 = acc[np * 2 + 3];
                MMA(d0, ah, bh0[0], bh0[1]);
                MMA(d1, ah, bh0[2], bh0[3]);
                MMA(d2, ah, bh1[0], bh1[1]);
                MMA(d3, ah, bh1[2], bh1[3]);
                MMA(d0, ah, bl0[0], bl0[1]);
                MMA(d1, ah, bl0[2], bl0[3]);
                MMA(d2, ah, bl1[0], bl1[1]);
                MMA(d3, ah, bl1[2], bl1[3]);
                MMA(d0, al, bh0[0], bh0[1]);
                MMA(d1, al, bh0[2], bh0[3]);
                MMA(d2, al, bh1[0], bh1[1]);
                MMA(d3, al, bh1[2], bh1[3]);
            }
        }
    }
    __syncthreads();   // all warps done reading X/W1 before H overlays them

    // ---- Epilogue 1: H = leaky(acc + b1), cols >=150 zeroed; bf16 hi/lo ----
    {
        const int rlo = m0 + (lane >> 2);
        const int cq = (lane & 3) * 2;
        #pragma unroll
        for (int nt = 0; nt < 20; nt++) {
            int c0 = nt * 8 + cq;
            float bb0 = (c0 < HID_C)     ? __ldg(b1 + c0)     : 0.f;
            float bb1 = (c0 + 1 < HID_C) ? __ldg(b1 + c0 + 1) : 0.f;
            float v0 = (c0 < HID_C)     ? leaky(acc[nt][0] + bb0) : 0.f;
            float v1 = (c0 + 1 < HID_C) ? leaky(acc[nt][1] + bb1) : 0.f;
            float v2 = (c0 < HID_C)     ? leaky(acc[nt][2] + bb0) : 0.f;
            float v3 = (c0 + 1 < HID_C) ? leaky(acc[nt][3] + bb1) : 0.f;
            uint32_t ph, pl;
            split2(v0, v1, ph, pl);
            *(uint32_t*)(smp + HH_O + rlo * 336 + c0 * 2) = ph;
            *(uint32_t*)(smp + HL_O + rlo * 336 + c0 * 2) = pl;
            split2(v2, v3, ph, pl);
            *(uint32_t*)(smp + HH_O + (rlo + 8) * 336 + c0 * 2) = ph;
            *(uint32_t*)(smp + HL_O + (rlo + 8) * 336 + c0 * 2) = pl;
        }
    }
    __syncwarp();   // warp reads only its own 16 H rows

    // ---- GEMM2: K = 160 (10 k-steps), N = 128 (16 tiles) ----
    float acc2[16][4];
    #pragma unroll
    for (int t = 0; t < 16; t++)
        #pragma unroll
        for (int r = 0; r < 4; r++) acc2[t][r] = 0.f;

    #pragma unroll
    for (int ks = 0; ks < 10; ks++) {
        const uint32_t off = ks * 32;
        uint32_t ah[4], al[4];
        LDSM4(ah, hh_a + off);
        LDSM4(al, hl_a + off);
        #pragma unroll
        for (int np = 0; np < 8; np += 2) {
            uint32_t bh0[4], bl0[4], bh1[4], bl1[4];
            LDSM4(bh0, w2h_b + np * 5376 + off);
            LDSM4(bl0, w2l_b + np * 5376 + off);
            LDSM4(bh1, w2h_b + (np + 1) * 5376 + off);
            LDSM4(bl1, w2l_b + (np + 1) * 5376 + off);
            float* d0 = acc2[np * 2 + 0];
            float* d1 = acc2[np * 2 + 1];
            float* d2 = acc2[np * 2 + 2];
            float* d3 = acc2[np * 2 + 3];
            MMA(d0, ah, bh0[0], bh0[1]);
            MMA(d1, ah, bh0[2], bh0[3]);
            MMA(d2, ah, bh1[0], bh1[1]);
            MMA(d3, ah, bh1[2], bh1[3]);
            MMA(d0, ah, bl0[0], bl0[1]);
            MMA(d1, ah, bl0[2], bl0[3]);
            MMA(d2, ah, bl1[0], bl1[1]);
            MMA(d3, ah, bl1[2], bl1[3]);
            MMA(d0, al, bh0[0], bh0[1]);
            MMA(d1, al, bh0[2], bh0[3]);
            MMA(d2, al, bh1[0], bh1[1]);
            MMA(d3, al, bh1[2], bh1[3]);
        }
    }

    // ---- Epilogue 2: te = leaky(acc2 + b2) -> gmem ----
    {
        const int rlo = row0 + m0 + (lane >> 2);
        const int cq = (lane & 3) * 2;
        #pragma unroll
        for (int nt = 0; nt < 16; nt++) {
            int c0 = nt * 8 + cq;
            float bb0 = __ldg(b2 + c0), bb1 = __ldg(b2 + c0 + 1);
            float2 vlo = make_float2(leaky(acc2[nt][0] + bb0), leaky(acc2[nt][1] + bb1));
            float2 vhi = make_float2(leaky(acc2[nt][2] + bb0), leaky(acc2[nt][3] + bb1));
            *(float2*)(g_te + (size_t)rlo * D_D + c0) = vlo;
            *(float2*)(g_te + (size_t)(rlo + 8) * D_D + c0) = vhi;
        }
    }
}

// ---------------------------------------------------------------------------
// Kernel 2: attention stage (one warp per (b,n))
// ---------------------------------------------------------------------------
__global__ __launch_bounds__(256) void attn_kernel(
    const int* __restrict__ batch,
    const float* __restrict__ user_table,
    const float* __restrict__ item_table,
    const float* __restrict__ aw1,
    const float* __restrict__ ab1,
    const float* __restrict__ aw2)
{
    __shared__ float sm_e[8][8];
    const int tid = threadIdx.x;
    const int w = tid >> 5, lane = tid & 31;
    const int b = blockIdx.x * 8 + w;
    const int n = blockIdx.y;
    const int bn = b * N_N + n;
    const int f = lane >> 3;
    const int s = lane & 7;

    const int user = batch[b * 6];
    const int item = batch[b * 6 + 1 + n];
    float4 u  = *(const float4*)(user_table + (size_t)user * D_D + lane * 4);
    float4 it = *(const float4*)(item_table + (size_t)item * D_D + lane * 4);
    float4 t  = *(const float4*)(g_te + (size_t)bn * D_D + lane * 4);

    float ss = u.x*u.x + u.y*u.y + u.z*u.z + u.w*u.w
             + it.x*it.x + it.y*it.y + it.z*it.z + it.w*it.w
             + t.x*t.x + t.y*t.y + t.z*t.z + t.w*t.w;
    float dui = u.x*it.x + u.y*it.y + u.z*it.z + u.w*it.w;
    float dut = u.x*t.x  + u.y*t.y  + u.z*t.z  + u.w*t.w;

    const float* A0 = aw1 + (f * 2 + 0) * 96;
    const float* A1 = aw1 + (f * 2 + 1) * 96;
    const int k0 = s * 4;
    float p0 = u.x*A0[k0] + u.y*A0[k0+1] + u.z*A0[k0+2] + u.w*A0[k0+3]
             + it.x*A0[32+k0] + it.y*A0[33+k0] + it.z*A0[34+k0] + it.w*A0[35+k0]
             + t.x*A0[64+k0]  + t.y*A0[65+k0]  + t.z*A0[66+k0]  + t.w*A0[67+k0];
    float p1 = u.x*A1[k0] + u.y*A1[k0+1] + u.z*A1[k0+2] + u.w*A1[k0+3]
             + it.x*A1[32+k0] + it.y*A1[33+k0] + it.z*A1[34+k0] + it.w*A1[35+k0]
             + t.x*A1[64+k0]  + t.y*A1[65+k0]  + t.z*A1[66+k0]  + t.w*A1[67+k0];

    #pragma unroll
    for (int m = 1; m < 8; m <<= 1) {
        ss  += __shfl_xor_sync(0xffffffffu, ss,  m);
        dui += __shfl_xor_sync(0xffffffffu, dui, m);
        dut += __shfl_xor_sync(0xffffffffu, dut, m);
        p0  += __shfl_xor_sync(0xffffffffu, p0,  m);
        p1  += __shfl_xor_sync(0xffffffffu, p1,  m);
    }

    float inv = 1.0f / fmaxf(sqrtf(ss), 1e-12f);
    float h0 = tanhf(p0 * inv + __ldg(ab1 + f * 2 + 0));
    float h1 = tanhf(p1 * inv + __ldg(ab1 + f * 2 + 1));
    float l0 = h0 * __ldg(aw2 + f * 4 + 0) + h1 * __ldg(aw2 + f * 4 + 1);
    float l1 = h0 * __ldg(aw2 + f * 4 + 2) + h1 * __ldg(aw2 + f * 4 + 3);
    float e0 = expf(l0), e1 = expf(l1);

    if (s == 0) {
        g_P[(size_t)bn * 8 + f * 2 + 0] = e0 * softplusf(dui);
        g_P[(size_t)bn * 8 + f * 2 + 1] = e1 * softplusf(dut);
        sm_e[w][f * 2 + 0] = e0;
        sm_e[w][f * 2 + 1] = e1;
    }
    __syncthreads();
    if (tid < 8) {
        float sum = 0.f;
        #pragma unroll
        for (int q = 0; q < 8; q++) sum += sm_e[q][tid];
        g_partial[(n * 8 + tid) * 2048 + blockIdx.x] = sum;
    }
}

// ---------------------------------------------------------------------------
// Kernel 2.5 + 3: deterministic denominator reduce, final combine
// ---------------------------------------------------------------------------
__global__ __launch_bounds__(256) void reduce_kernel()
{
    __shared__ float sm[256];
    const int q = blockIdx.x;
    float s = 0.f;
    for (int i = threadIdx.x; i < 2048; i += 256)
        s += g_partial[q * 2048 + i];
    sm[threadIdx.x] = s;
    __syncthreads();
    for (int st = 128; st > 0; st >>= 1) {
        if (threadIdx.x < st) sm[threadIdx.x] += sm[threadIdx.x + st];
        __syncthreads();
    }
    if (threadIdx.x == 0) g_invS[q] = 1.0f / sm[0];
}

__global__ __launch_bounds__(256) void final_kernel(float* __restrict__ out)
{
    const int idx = blockIdx.x * 256 + threadIdx.x;
    if (idx >= R_R) return;
    const int n = idx % N_N;
    float r = 0.f;
    #pragma unroll
    for (int f = 0; f < 4; f++) {
        r += g_P[(size_t)idx * 8 + f * 2 + 0] * g_invS[n * 8 + f * 2 + 0];
        r += g_P[(size_t)idx * 8 + f * 2 + 1] * g_invS[n * 8 + f * 2 + 1];
    }
    out[idx] = r;
}

// ---------------------------------------------------------------------------
extern "C" void kernel_launch(void* const* d_in, const int* in_sizes, int n_in,
                              void* d_out, int out_size)
{
    const int*   batch = (const int*)d_in[0];
    const float* text  = (const float*)d_in[1];
    const float* ut    = (const float*)d_in[2];
    const float* itt   = (const float*)d_in[3];
    const float* w1    = (const float*)d_in[4];
    const float* b1    = (const float*)d_in[5];
    const float* w2    = (const float*)d_in[6];
    const float* b2    = (const float*)d_in[7];
    const float* aw1   = (const float*)d_in[8];
    const float* ab1   = (const float*)d_in[9];
    const float* aw2   = (const float*)d_in[10];
    float* out = (float*)d_out;

    cudaFuncSetAttribute(mlp_mma_kernel, cudaFuncAttributeMaxDynamicSharedMemorySize, SMEM_BYTES);

    setup_kernel<<<(160 * 384 + 128 * 192 + 255) / 256, 256>>>(w1, w2);
    mlp_mma_kernel<<<R_R / MROWS, 256, SMEM_BYTES>>>(text, b1, b2);
    attn_kernel<<<dim3(B_SZ / 8, N_N), 256>>>(batch, ut, itt, aw1, ab1, aw2);
    reduce_kernel<<<40, 256>>>();
    final_kernel<<<(R_R + 255) / 256, 256>>>(out);
}

// round 4
// speedup vs baseline: 2.6903x; 1.1702x over previous
#include <cuda_runtime.h>
#include <cuda_bf16.h>
#include <cstdint>
#include <cstddef>

// ---------------------------------------------------------------------------
// Problem constants
// ---------------------------------------------------------------------------
#define B_SZ   16384
#define N_N    5
#define D_D    128
#define TD_D   384
#define HID_C  150
#define R_R    (B_SZ * N_N)     // 81920 MLP rows
#define MROWS  128              // rows per CTA

// ---------------------------------------------------------------------------
// Device scratch
// ---------------------------------------------------------------------------
__device__ float g_te[(size_t)R_R * D_D];
__device__ float g_P[(size_t)R_R * 8];
__device__ float g_partial[5 * 8 * 2048];
__device__ float g_invS[40];
__device__ __align__(16) __nv_bfloat16 g_w1h[160 * 384];  // W1 hi, rows 150..159 zero
__device__ __align__(16) __nv_bfloat16 g_w1l[160 * 384];  // W1 lo
__device__ __align__(16) __nv_bfloat16 g_w2h[128 * 192];  // W2 hi, cols 150..191 zero
__device__ __align__(16) __nv_bfloat16 g_w2l[128 * 192];  // W2 lo

__device__ __forceinline__ float leaky(float x) { return x > 0.f ? x : 0.01f * x; }
__device__ __forceinline__ float softplusf(float x) {
    return fmaxf(x, 0.f) + log1pf(expf(-fabsf(x)));
}

// ---------------------------------------------------------------------------
// MMA helpers (portable PTX, valid on plain sm_103 target)
// ---------------------------------------------------------------------------
#define LDSM4(r, a)                                                            \
    asm volatile("ldmatrix.sync.aligned.m8n8.x4.shared.b16 {%0,%1,%2,%3}, [%4];" \
        : "=r"((r)[0]), "=r"((r)[1]), "=r"((r)[2]), "=r"((r)[3]) : "r"(a))

#define MMA(d, a, b0_, b1_)                                                    \
    asm volatile("mma.sync.aligned.m16n8k16.row.col.f32.bf16.bf16.f32 "        \
        "{%0,%1,%2,%3}, {%4,%5,%6,%7}, {%8,%9}, {%0,%1,%2,%3};"                \
        : "+f"((d)[0]), "+f"((d)[1]), "+f"((d)[2]), "+f"((d)[3])               \
        : "r"((a)[0]), "r"((a)[1]), "r"((a)[2]), "r"((a)[3]), "r"(b0_), "r"(b1_))

__device__ __forceinline__ uint32_t smem_u32(const void* p) {
    uint32_t a;
    asm("{ .reg .u64 t; cvta.to.shared.u64 t, %1; cvt.u32.u64 %0, t; }" : "=r"(a) : "l"(p));
    return a;
}

// Split two fp32 into packed bf16x2 (hi) + packed bf16x2 (residual).
// Low 16 bits hold v0 (memory order).
__device__ __forceinline__ void split2(float v0, float v1, uint32_t& ph, uint32_t& pl) {
    asm("cvt.rn.bf16x2.f32 %0, %1, %2;" : "=r"(ph) : "f"(v1), "f"(v0));
    float h0 = __uint_as_float(ph << 16);
    float h1 = __uint_as_float(ph & 0xffff0000u);
    float r0 = v0 - h0, r1 = v1 - h1;
    asm("cvt.rn.bf16x2.f32 %0, %1, %2;" : "=r"(pl) : "f"(r1), "f"(r0));
}

__device__ __forceinline__ void split_bf16s(float x, unsigned short& h, unsigned short& l) {
    __nv_bfloat16 bh = __float2bfloat16(x);
    float r = x - __bfloat162float(bh);
    h = __bfloat16_as_ushort(bh);
    l = __bfloat16_as_ushort(__float2bfloat16(r));
}

// ---------------------------------------------------------------------------
// Shared memory map (byte offsets; strides 144/336 are ldmatrix conflict-free)
// Phase 1 (double-buffered K-chunks of 64):
//   X buf b:  hi at XB(b), lo at XB(b)+18432       (128 rows x 144B)
//   W1 buf b: hi at W1B(b), lo at W1B(b)+23040     (160 rows x 144B)
//   -> phase-1 footprint 165,888 B
// Phase 2 (overlays phase 1 after GEMM1):
//   H  hi 0, lo 43008                              (128 rows x 336B)
//   W2 hi 86016, lo 129024                         (128 rows x 336B)
// ---------------------------------------------------------------------------
#define XB(b)   ((b) * 36864u)
#define W1B(b)  (73728u + (b) * 46080u)
#define HH_O    0u
#define HL_O    43008u
#define W2H_O   86016u
#define W2L_O   129024u
#define SMEM_BYTES 172032

// ---------------------------------------------------------------------------
// Kernel 0: split W1/W2 into bf16 hi/lo with zero padding
// ---------------------------------------------------------------------------
__global__ __launch_bounds__(256) void setup_kernel(
    const float* __restrict__ w1, const float* __restrict__ w2)
{
    int i = blockIdx.x * 256 + threadIdx.x;
    if (i < 160 * 384) {
        int r = i / 384, c = i % 384;
        float v = (r < HID_C) ? w1[r * TD_D + c] : 0.f;
        unsigned short h, l;
        split_bf16s(v, h, l);
        g_w1h[i] = __ushort_as_bfloat16(h);
        g_w1l[i] = __ushort_as_bfloat16(l);
    } else {
        int j = i - 160 * 384;
        if (j < 128 * 192) {
            int r = j / 192, c = j % 192;
            float v = (c < HID_C) ? w2[r * HID_C + c] : 0.f;
            unsigned short h, l;
            split_bf16s(v, h, l);
            g_w2h[j] = __ushort_as_bfloat16(h);
            g_w2l[j] = __ushort_as_bfloat16(l);
        }
    }
}

// ---------------------------------------------------------------------------
// Kernel 1: fused text MLP, mma.sync bf16 3-term split, fp32 accumulate.
// 8 warps in a 4M x 2N grid: warp owns 32 rows x 80 cols (GEMM1) / 64 (GEMM2).
// K-chunks double-buffered; next chunk's text prefetched into regs during MMA.
// ---------------------------------------------------------------------------
__global__ __launch_bounds__(256, 1)
void mlp_mma_kernel(const float* __restrict__ text,
                    const float* __restrict__ b1,
                    const float* __restrict__ b2)
{
    extern __shared__ __align__(16) char smp[];
    const uint32_t s0 = smem_u32(smp);

    const int tid = threadIdx.x;
    const int wid = tid >> 5, lane = tid & 31;
    const int row0 = blockIdx.x * MROWS;

    const int mg = wid >> 1, ng = wid & 1;
    const int m0 = mg * 32;
    const int n0g1 = ng * 80;    // GEMM1 col offset
    const int n0g2 = ng * 64;    // GEMM2 col offset

    // ldmatrix lane address components
    const uint32_t a_row  = (lane & 7) + ((lane >> 3) & 1) * 8;
    const uint32_t a_col8 = (uint32_t)(lane >> 4) * 8;
    const uint32_t b_row  = (lane & 7) + (lane >> 4) * 8;
    const uint32_t b_col8 = (uint32_t)((lane >> 3) & 1) * 8;

    const uint32_t aoff1 = (m0 + a_row) * 144 + a_col8 * 2;           // in X buf
    const uint32_t boff1 = (n0g1 + b_row) * 144 + b_col8 * 2;         // in W1 buf
    const uint32_t hh_a  = s0 + HH_O + (m0 + a_row) * 336 + a_col8 * 2;
    const uint32_t hl_a  = s0 + HL_O + (m0 + a_row) * 336 + a_col8 * 2;
    const uint32_t w2h_b = s0 + W2H_O + (n0g2 + b_row) * 336 + b_col8 * 2;
    const uint32_t w2l_b = s0 + W2L_O + (n0g2 + b_row) * 336 + b_col8 * 2;

    // X converter mapping: each thread converts one row-half (32 floats)
    const int xr   = tid >> 1;
    const int xh32 = (tid & 1) * 32;
    const float* xsrc = text + (size_t)(row0 + xr) * TD_D + xh32;

    // ---- GEMM1: 6 K-chunks of 64, double-buffered, reg-prefetched ----
    float acc[2][10][4];
    #pragma unroll
    for (int mt = 0; mt < 2; mt++)
        #pragma unroll
        for (int nt = 0; nt < 10; nt++)
            #pragma unroll
            for (int r = 0; r < 4; r++) acc[mt][nt][r] = 0.f;

    float4 pf[8];
    #pragma unroll
    for (int i = 0; i < 8; i++) pf[i] = *(const float4*)(xsrc + i * 4);

    for (int kc = 0; kc < 6; kc++) {
        const int buf = kc & 1;
        // store converted X chunk (from prefetch regs)
        {
            char* dh = smp + XB(buf) + xr * 144 + xh32 * 2;
            char* dl = dh + 18432;
            #pragma unroll
            for (int i = 0; i < 8; i++) {
                uint32_t pha, pla, phb, plb;
                split2(pf[i].x, pf[i].y, pha, pla);
                split2(pf[i].z, pf[i].w, phb, plb);
                *(uint2*)(dh + i * 8) = make_uint2(pha, phb);
                *(uint2*)(dl + i * 8) = make_uint2(pla, plb);
            }
        }
        // W1 chunk copy (pre-split bf16)
        {
            char* wh = smp + W1B(buf);
            char* wl = wh + 23040;
            #pragma unroll
            for (int j = 0; j < 5; j++) {
                int idx = tid + j * 256;           // < 1280
                int r = idx >> 3, seg = idx & 7;
                *(uint4*)(wh + r * 144 + seg * 16) =
                    *(const uint4*)(g_w1h + r * 384 + kc * 64 + seg * 8);
                *(uint4*)(wl + r * 144 + seg * 16) =
                    *(const uint4*)(g_w1l + r * 384 + kc * 64 + seg * 8);
            }
        }
        __syncthreads();

        // prefetch next chunk's text into registers (overlaps MMA burst)
        if (kc < 5) {
            #pragma unroll
            for (int i = 0; i < 8; i++)
                pf[i] = *(const float4*)(xsrc + (kc + 1) * 64 + i * 4);
        }

        const uint32_t xa  = s0 + XB(buf) + aoff1;
        const uint32_t w1b = s0 + W1B(buf) + boff1;
        #pragma unroll
        for (int ks = 0; ks < 4; ks++) {
            const uint32_t off = ks * 32;
            uint32_t ah0[4], ah1[4], al0[4], al1[4];
            LDSM4(ah0, xa + off);
            LDSM4(ah1, xa + 2304 + off);
            LDSM4(al0, xa + 18432 + off);
            LDSM4(al1, xa + 18432 + 2304 + off);
            #pragma unroll
            for (int p = 0; p < 5; p++) {
                uint32_t bh[4], bl[4];
                LDSM4(bh, w1b + p * 2304 + off);
                LDSM4(bl, w1b + 23040 + p * 2304 + off);
                float* d00 = acc[0][2 * p];
                float* d01 = acc[0][2 * p + 1];
                float* d10 = acc[1][2 * p];
                float* d11 = acc[1][2 * p + 1];
                MMA(d00, ah0, bh[0], bh[1]);
                MMA(d01, ah0, bh[2], bh[3]);
                MMA(d10, ah1, bh[0], bh[1]);
                MMA(d11, ah1, bh[2], bh[3]);
                MMA(d00, ah0, bl[0], bl[1]);
                MMA(d01, ah0, bl[2], bl[3]);
                MMA(d10, ah1, bl[0], bl[1]);
                MMA(d11, ah1, bl[2], bl[3]);
                MMA(d00, al0, bh[0], bh[1]);
                MMA(d01, al0, bh[2], bh[3]);
                MMA(d10, al1, bh[0], bh[1]);
                MMA(d11, al1, bh[2], bh[3]);
            }
        }
    }
    __syncthreads();   // GEMM1 reads done; H/W2 overlay phase-1 buffers

    // ---- Epilogue 1: H = leaky(acc + b1) (cols >= 150 zero) -> smem hi/lo ----
    {
        const int rl = lane >> 2, cq = (lane & 3) * 2;
        #pragma unroll
        for (int mt = 0; mt < 2; mt++) {
            const int r = m0 + mt * 16 + rl;
            #pragma unroll
            for (int nt = 0; nt < 10; nt++) {
                int c0 = n0g1 + nt * 8 + cq;
                float bb0 = (c0 < HID_C)     ? __ldg(b1 + c0)     : 0.f;
                float bb1 = (c0 + 1 < HID_C) ? __ldg(b1 + c0 + 1) : 0.f;
                float v0 = (c0 < HID_C)     ? leaky(acc[mt][nt][0] + bb0) : 0.f;
                float v1 = (c0 + 1 < HID_C) ? leaky(acc[mt][nt][1] + bb1) : 0.f;
                float v2 = (c0 < HID_C)     ? leaky(acc[mt][nt][2] + bb0) : 0.f;
                float v3 = (c0 + 1 < HID_C) ? leaky(acc[mt][nt][3] + bb1) : 0.f;
                uint32_t ph, pl;
                split2(v0, v1, ph, pl);
                *(uint32_t*)(smp + HH_O + r * 336 + c0 * 2) = ph;
                *(uint32_t*)(smp + HL_O + r * 336 + c0 * 2) = pl;
                split2(v2, v3, ph, pl);
                *(uint32_t*)(smp + HH_O + (r + 8) * 336 + c0 * 2) = ph;
                *(uint32_t*)(smp + HL_O + (r + 8) * 336 + c0 * 2) = pl;
            }
        }
    }
    // ---- W2 panel into smem (hi/lo), 128 rows x 160 k, stride 336 ----
    #pragma unroll
    for (int j = 0; j < 10; j++) {
        int idx = tid + j * 256;               // < 2560
        int r = idx / 20, seg = idx % 20;
        *(uint4*)(smp + W2H_O + r * 336 + seg * 16) =
            *(const uint4*)(g_w2h + r * 192 + seg * 8);
        *(uint4*)(smp + W2L_O + r * 336 + seg * 16) =
            *(const uint4*)(g_w2l + r * 192 + seg * 8);
    }
    __syncthreads();

    // ---- GEMM2: K = 160 (10 k-steps), warp covers 32 rows x 64 cols ----
    float acc2[2][8][4];
    #pragma unroll
    for (int mt = 0; mt < 2; mt++)
        #pragma unroll
        for (int nt = 0; nt < 8; nt++)
            #pragma unroll
            for (int r = 0; r < 4; r++) acc2[mt][nt][r] = 0.f;

    #pragma unroll
    for (int ks = 0; ks < 10; ks++) {
        const uint32_t off = ks * 32;
        uint32_t ah0[4], ah1[4], al0[4], al1[4];
        LDSM4(ah0, hh_a + off);
        LDSM4(ah1, hh_a + 5376 + off);
        LDSM4(al0, hl_a + off);
        LDSM4(al1, hl_a + 5376 + off);
        #pragma unroll
        for (int p = 0; p < 4; p++) {
            uint32_t bh[4], bl[4];
            LDSM4(bh, w2h_b + p * 5376 + off);
            LDSM4(bl, w2l_b + p * 5376 + off);
            float* d00 = acc2[0][2 * p];
            float* d01 = acc2[0][2 * p + 1];
            float* d10 = acc2[1][2 * p];
            float* d11 = acc2[1][2 * p + 1];
            MMA(d00, ah0, bh[0], bh[1]);
            MMA(d01, ah0, bh[2], bh[3]);
            MMA(d10, ah1, bh[0], bh[1]);
            MMA(d11, ah1, bh[2], bh[3]);
            MMA(d00, ah0, bl[0], bl[1]);
            MMA(d01, ah0, bl[2], bl[3]);
            MMA(d10, ah1, bl[0], bl[1]);
            MMA(d11, ah1, bl[2], bl[3]);
            MMA(d00, al0, bh[0], bh[1]);
            MMA(d01, al0, bh[2], bh[3]);
            MMA(d10, al1, bh[0], bh[1]);
            MMA(d11, al1, bh[2], bh[3]);
        }
    }

    // ---- Epilogue 2: te = leaky(acc2 + b2) -> gmem ----
    {
        const int rl = lane >> 2, cq = (lane & 3) * 2;
        #pragma unroll
        for (int mt = 0; mt < 2; mt++) {
            const int r = row0 + m0 + mt * 16 + rl;
            #pragma unroll
            for (int nt = 0; nt < 8; nt++) {
                int c0 = n0g2 + nt * 8 + cq;
                float bb0 = __ldg(b2 + c0), bb1 = __ldg(b2 + c0 + 1);
                float2 vlo = make_float2(leaky(acc2[mt][nt][0] + bb0),
                                         leaky(acc2[mt][nt][1] + bb1));
                float2 vhi = make_float2(leaky(acc2[mt][nt][2] + bb0),
                                         leaky(acc2[mt][nt][3] + bb1));
                *(float2*)(g_te + (size_t)r * D_D + c0) = vlo;
                *(float2*)(g_te + (size_t)(r + 8) * D_D + c0) = vhi;
            }
        }
    }
}

// ---------------------------------------------------------------------------
// Kernel 2: attention stage (one warp per (b,n))
// ---------------------------------------------------------------------------
__global__ __launch_bounds__(256) void attn_kernel(
    const int* __restrict__ batch,
    const float* __restrict__ user_table,
    const float* __restrict__ item_table,
    const float* __restrict__ aw1,
    const float* __restrict__ ab1,
    const float* __restrict__ aw2)
{
    __shared__ float sm_e[8][8];
    const int tid = threadIdx.x;
    const int w = tid >> 5, lane = tid & 31;
    const int b = blockIdx.x * 8 + w;
    const int n = blockIdx.y;
    const int bn = b * N_N + n;
    const int f = lane >> 3;
    const int s = lane & 7;

    const int user = batch[b * 6];
    const int item = batch[b * 6 + 1 + n];
    float4 u  = *(const float4*)(user_table + (size_t)user * D_D + lane * 4);
    float4 it = *(const float4*)(item_table + (size_t)item * D_D + lane * 4);
    float4 t  = *(const float4*)(g_te + (size_t)bn * D_D + lane * 4);

    float ss = u.x*u.x + u.y*u.y + u.z*u.z + u.w*u.w
             + it.x*it.x + it.y*it.y + it.z*it.z + it.w*it.w
             + t.x*t.x + t.y*t.y + t.z*t.z + t.w*t.w;
    float dui = u.x*it.x + u.y*it.y + u.z*it.z + u.w*it.w;
    float dut = u.x*t.x  + u.y*t.y  + u.z*t.z  + u.w*t.w;

    const float* A0 = aw1 + (f * 2 + 0) * 96;
    const float* A1 = aw1 + (f * 2 + 1) * 96;
    const int k0 = s * 4;
    float p0 = u.x*A0[k0] + u.y*A0[k0+1] + u.z*A0[k0+2] + u.w*A0[k0+3]
             + it.x*A0[32+k0] + it.y*A0[33+k0] + it.z*A0[34+k0] + it.w*A0[35+k0]
             + t.x*A0[64+k0]  + t.y*A0[65+k0]  + t.z*A0[66+k0]  + t.w*A0[67+k0];
    float p1 = u.x*A1[k0] + u.y*A1[k0+1] + u.z*A1[k0+2] + u.w*A1[k0+3]
             + it.x*A1[32+k0] + it.y*A1[33+k0] + it.z*A1[34+k0] + it.w*A1[35+k0]
             + t.x*A1[64+k0]  + t.y*A1[65+k0]  + t.z*A1[66+k0]  + t.w*A1[67+k0];

    #pragma unroll
    for (int m = 1; m < 8; m <<= 1) {
        ss  += __shfl_xor_sync(0xffffffffu, ss,  m);
        dui += __shfl_xor_sync(0xffffffffu, dui, m);
        dut += __shfl_xor_sync(0xffffffffu, dut, m);
        p0  += __shfl_xor_sync(0xffffffffu, p0,  m);
        p1  += __shfl_xor_sync(0xffffffffu, p1,  m);
    }

    float inv = 1.0f / fmaxf(sqrtf(ss), 1e-12f);
    float h0 = tanhf(p0 * inv + __ldg(ab1 + f * 2 + 0));
    float h1 = tanhf(p1 * inv + __ldg(ab1 + f * 2 + 1));
    float l0 = h0 * __ldg(aw2 + f * 4 + 0) + h1 * __ldg(aw2 + f * 4 + 1);
    float l1 = h0 * __ldg(aw2 + f * 4 + 2) + h1 * __ldg(aw2 + f * 4 + 3);
    float e0 = expf(l0), e1 = expf(l1);

    if (s == 0) {
        g_P[(size_t)bn * 8 + f * 2 + 0] = e0 * softplusf(dui);
        g_P[(size_t)bn * 8 + f * 2 + 1] = e1 * softplusf(dut);
        sm_e[w][f * 2 + 0] = e0;
        sm_e[w][f * 2 + 1] = e1;
    }
    __syncthreads();
    if (tid < 8) {
        float sum = 0.f;
        #pragma unroll
        for (int q = 0; q < 8; q++) sum += sm_e[q][tid];
        g_partial[(n * 8 + tid) * 2048 + blockIdx.x] = sum;
    }
}

// ---------------------------------------------------------------------------
// Kernel 2.5 + 3: deterministic denominator reduce, final combine
// ---------------------------------------------------------------------------
__global__ __launch_bounds__(256) void reduce_kernel()
{
    __shared__ float sm[256];
    const int q = blockIdx.x;
    float s = 0.f;
    for (int i = threadIdx.x; i < 2048; i += 256)
        s += g_partial[q * 2048 + i];
    sm[threadIdx.x] = s;
    __syncthreads();
    for (int st = 128; st > 0; st >>= 1) {
        if (threadIdx.x < st) sm[threadIdx.x] += sm[threadIdx.x + st];
        __syncthreads();
    }
    if (threadIdx.x == 0) g_invS[q] = 1.0f / sm[0];
}

__global__ __launch_bounds__(256) void final_kernel(float* __restrict__ out)
{
    const int idx = blockIdx.x * 256 + threadIdx.x;
    if (idx >= R_R) return;
    const int n = idx % N_N;
    float r = 0.f;
    #pragma unroll
    for (int f = 0; f < 4; f++) {
        r += g_P[(size_t)idx * 8 + f * 2 + 0] * g_invS[n * 8 + f * 2 + 0];
        r += g_P[(size_t)idx * 8 + f * 2 + 1] * g_invS[n * 8 + f * 2 + 1];
    }
    out[idx] = r;
}

// ---------------------------------------------------------------------------
extern "C" void kernel_launch(void* const* d_in, const int* in_sizes, int n_in,
                              void* d_out, int out_size)
{
    const int*   batch = (const int*)d_in[0];
    const float* text  = (const float*)d_in[1];
    const float* ut    = (const float*)d_in[2];
    const float* itt   = (const float*)d_in[3];
    const float* w1    = (const float*)d_in[4];
    const float* b1    = (const float*)d_in[5];
    const float* w2    = (const float*)d_in[6];
    const float* b2    = (const float*)d_in[7];
    const float* aw1   = (const float*)d_in[8];
    const float* ab1   = (const float*)d_in[9];
    const float* aw2   = (const float*)d_in[10];
    float* out = (float*)d_out;

    cudaFuncSetAttribute(mlp_mma_kernel, cudaFuncAttributeMaxDynamicSharedMemorySize, SMEM_BYTES);

    setup_kernel<<<(160 * 384 + 128 * 192 + 255) / 256, 256>>>(w1, w2);
    mlp_mma_kernel<<<R_R / MROWS, 256, SMEM_BYTES>>>(text, b1, b2);
    attn_kernel<<<dim3(B_SZ / 8, N_N), 256>>>(batch, ut, itt, aw1, ab1, aw2);
    reduce_kernel<<<40, 256>>>();
    final_kernel<<<(R_R + 255) / 256, 256>>>(out);
}